// round 1
// baseline (speedup 1.0000x reference)
#include <cuda_runtime.h>
#include <cstdint>
#include <cstddef>

#define B_   8
#define T_   200
#define U_   50
#define V_   1024
#define UM1  (U_ - 1)

#define LOG2E 1.4426950408889634f
#define LN2   0.6931471805599453f
#define NEGINF (-1e30f)

// Scratch (allocation-free: __device__ globals)
__device__ float g_blank[B_ * T_ * U_];    // (b,t,u), log2-domain: (h - lse) * log2(e)
__device__ float g_emit [B_ * T_ * UM1];   // (b,t,u), log2-domain
__device__ float g_res  [B_];              // per-batch -final (natural log)

// ---------------------------------------------------------------------------
// Kernel A: per-(b,u) gather of the two needed vocab columns + logsumexp over T.
// Grid: B*U blocks, 256 threads (thread t handles time step t, t<T).
// ---------------------------------------------------------------------------
__global__ __launch_bounds__(256) void k_lse(const float* __restrict__ h,
                                             const int*   __restrict__ targets) {
    const int bu = blockIdx.x;
    const int b  = bu / U_;
    const int u  = bu % U_;
    const int t  = threadIdx.x;
    const bool hasE = (u < UM1);
    const int  tgt  = hasE ? targets[b * UM1 + u] : 0;

    const float* col = h + ((size_t)b * T_ * U_ + (size_t)u) * V_;

    float vb = NEGINF, ve = NEGINF;
    if (t < T_) {
        const size_t off = (size_t)t * (U_ * V_);
        vb = col[off];                         // blank column  (v = 0)
        if (hasE) ve = col[off + tgt];         // emit column   (v = targets[b,u])
    }

    __shared__ float s0[8], s1[8];
    const int wid  = threadIdx.x >> 5;
    const int lane = threadIdx.x & 31;

    // ---- block max (two values at once) ----
    float m0 = vb, m1 = ve;
    #pragma unroll
    for (int o = 16; o > 0; o >>= 1) {
        m0 = fmaxf(m0, __shfl_xor_sync(0xffffffffu, m0, o));
        m1 = fmaxf(m1, __shfl_xor_sync(0xffffffffu, m1, o));
    }
    if (lane == 0) { s0[wid] = m0; s1[wid] = m1; }
    __syncthreads();
    float M0 = s0[0], M1 = s1[0];
    #pragma unroll
    for (int i = 1; i < 8; ++i) { M0 = fmaxf(M0, s0[i]); M1 = fmaxf(M1, s1[i]); }

    // ---- block sum of exp(v - max) ----
    float e0 = (t < T_) ? __expf(vb - M0) : 0.0f;
    float e1 = (t < T_ && hasE) ? __expf(ve - M1) : 0.0f;
    #pragma unroll
    for (int o = 16; o > 0; o >>= 1) {
        e0 += __shfl_xor_sync(0xffffffffu, e0, o);
        e1 += __shfl_xor_sync(0xffffffffu, e1, o);
    }
    __syncthreads();               // s0/s1 reuse
    if (lane == 0) { s0[wid] = e0; s1[wid] = e1; }
    __syncthreads();
    float S0 = 0.0f, S1 = 0.0f;
    #pragma unroll
    for (int i = 0; i < 8; ++i) { S0 += s0[i]; S1 += s1[i]; }

    const float lse0 = M0 + __logf(S0);
    const float lse1 = M1 + __logf(S1);   // unused (garbage) when !hasE

    if (t < T_) {
        g_blank[(b * T_ + t) * U_ + u] = (vb - lse0) * LOG2E;
        if (hasE) g_emit[(b * T_ + t) * UM1 + u] = (ve - lse1) * LOG2E;
    }
}

// ---------------------------------------------------------------------------
// Kernel B: anti-diagonal wavefront DP, one block per batch, one warp does DP.
// Lane i owns u = i and u = i+32; neighbor alpha via warp shuffles (no bar).
// All values in log2 domain; logaddexp2(x,y) = m + log2(1 + exp2(min-m)).
// ---------------------------------------------------------------------------
__global__ __launch_bounds__(256) void k_dp(const int* __restrict__ ilen,
                                            const int* __restrict__ tlen) {
    const int b = blockIdx.x;
    extern __shared__ float smem[];
    float* sb = smem;              // [T_][U_]
    float* se = smem + T_ * U_;    // [T_][UM1]

    {
        const float* gb = g_blank + b * T_ * U_;
        const float* ge = g_emit  + b * T_ * UM1;
        for (int i = threadIdx.x; i < T_ * U_;  i += 256) sb[i] = gb[i];
        for (int i = threadIdx.x; i < T_ * UM1; i += 256) se[i] = ge[i];
    }
    __syncthreads();
    if (threadIdx.x >= 32) return;      // warp 0 only from here

    const int lane = threadIdx.x;
    const int ti = ilen[b] - 1;         // in [99, 199]
    const int ui = tlen[b] - 1;         // in [24, 49]
    const int u0 = lane;
    const int u1 = lane + 32;

    float p0 = (lane == 0) ? 0.0f : NEGINF;   // alpha on diagonal d-1 for u0
    float p1 = NEGINF;                        // ... for u1

    const int dmax = ti + ui;                 // cell (ti,ui) lies on this diagonal
    #pragma unroll 2
    for (int d = 1; d <= dmax; ++d) {
        // previous-diagonal left neighbors
        float l0 = __shfl_up_sync(0xffffffffu, p0, 1);   // alpha[., u0-1]
        float l1 = __shfl_up_sync(0xffffffffu, p1, 1);   // alpha[., u1-1]
        float lw = __shfl_sync(0xffffffffu, p0, 31);     // lane31 u0=31 -> u1=32's left
        if (lane == 0) l1 = lw;

        float n0 = NEGINF, n1 = NEGINF;

        const int t0 = d - u0;
        if (t0 >= 0 && t0 < T_) {
            float x = (t0 >= 1) ? p0 + sb[(t0 - 1) * U_ + u0] : NEGINF;
            float y = (u0 >= 1) ? l0 + se[t0 * UM1 + (u0 - 1)] : NEGINF;
            float m = fmaxf(x, y);
            float z = fminf(x, y) - m;
            n0 = m + __log2f(1.0f + exp2f(z));
            if (t0 == ti && u0 == ui)
                g_res[b] = -(n0 + sb[t0 * U_ + u0]) * LN2;
        }

        const int t1 = d - u1;
        if (u1 < U_ && t1 >= 0 && t1 < T_) {
            float x = (t1 >= 1) ? p1 + sb[(t1 - 1) * U_ + u1] : NEGINF;
            float y = l1 + se[t1 * UM1 + (u1 - 1)];     // u1 >= 32 >= 1 always
            float m = fmaxf(x, y);
            float z = fminf(x, y) - m;
            n1 = m + __log2f(1.0f + exp2f(z));
            if (t1 == ti && u1 == ui)
                g_res[b] = -(n1 + sb[t1 * U_ + u1]) * LN2;
        }

        p0 = n0;
        p1 = n1;
    }
}

// ---------------------------------------------------------------------------
// Kernel C: deterministic mean over the 8 batches.
// ---------------------------------------------------------------------------
__global__ void k_final(float* __restrict__ out) {
    if (threadIdx.x == 0) {
        float s = 0.0f;
        #pragma unroll
        for (int i = 0; i < B_; ++i) s += g_res[i];
        out[0] = s * (1.0f / B_);
    }
}

// ---------------------------------------------------------------------------
extern "C" void kernel_launch(void* const* d_in, const int* in_sizes, int n_in,
                              void* d_out, int out_size) {
    const float* h       = (const float*)d_in[0];
    const int*   targets = (const int*)  d_in[1];
    const int*   il      = (const int*)  d_in[2];
    const int*   tl      = (const int*)  d_in[3];
    float*       out     = (float*)d_out;

    const int smem_bytes = (T_ * U_ + T_ * UM1) * (int)sizeof(float);  // 79200
    cudaFuncSetAttribute(k_dp, cudaFuncAttributeMaxDynamicSharedMemorySize, smem_bytes);

    k_lse  <<<B_ * U_, 256>>>(h, targets);
    k_dp   <<<B_, 256, smem_bytes>>>(il, tl);
    k_final<<<1, 32>>>(out);
}

// round 2
// speedup vs baseline: 1.0006x; 1.0006x over previous
#include <cuda_runtime.h>
#include <cstdint>
#include <cstddef>

#define B_   8
#define T_   200
#define U_   50
#define V_   1024
#define UM1  (U_ - 1)

#define LOG2E 1.4426950408889634f
#define LN2   0.6931471805599453f
#define NEGINF (-1e30f)

// Scratch (allocation-free: __device__ globals)
__device__ float g_blank[B_ * T_ * U_];    // (b,t,u), log2-domain: (h - lse) * log2(e)
__device__ float g_emit [B_ * T_ * UM1];   // (b,t,u), log2-domain
__device__ float g_res  [B_];              // per-batch -final (natural log)

__device__ __forceinline__ float ex2a(float x) {
    float r; asm("ex2.approx.f32 %0, %1;" : "=f"(r) : "f"(x)); return r;
}
__device__ __forceinline__ float lg2a(float x) {
    float r; asm("lg2.approx.f32 %0, %1;" : "=f"(r) : "f"(x)); return r;
}
// logaddexp2 with short critical path: fmax || (sub -> EX2(-|d|) -> add -> LG2 -> add)
__device__ __forceinline__ float lae2(float x, float y) {
    float m = fmaxf(x, y);
    float z = -fabsf(x - y);
    return m + lg2a(1.0f + ex2a(z));
}

// ---------------------------------------------------------------------------
// Kernel A: per-(b,u) gather of the two needed vocab columns + logsumexp over T.
// Grid: B*U blocks, 256 threads (thread t handles time step t, t<T).
// ---------------------------------------------------------------------------
__global__ __launch_bounds__(256) void k_lse(const float* __restrict__ h,
                                             const int*   __restrict__ targets) {
    const int bu = blockIdx.x;
    const int b  = bu / U_;
    const int u  = bu % U_;
    const int t  = threadIdx.x;
    const bool hasE = (u < UM1);
    const int  tgt  = hasE ? targets[b * UM1 + u] : 0;

    const float* col = h + ((size_t)b * T_ * U_ + (size_t)u) * V_;

    float vb = NEGINF, ve = NEGINF;
    if (t < T_) {
        const size_t off = (size_t)t * (U_ * V_);
        vb = col[off];                         // blank column  (v = 0)
        if (hasE) ve = col[off + tgt];         // emit column   (v = targets[b,u])
    }

    __shared__ float s0[8], s1[8];
    const int wid  = threadIdx.x >> 5;
    const int lane = threadIdx.x & 31;

    // ---- block max (two values at once) ----
    float m0 = vb, m1 = ve;
    #pragma unroll
    for (int o = 16; o > 0; o >>= 1) {
        m0 = fmaxf(m0, __shfl_xor_sync(0xffffffffu, m0, o));
        m1 = fmaxf(m1, __shfl_xor_sync(0xffffffffu, m1, o));
    }
    if (lane == 0) { s0[wid] = m0; s1[wid] = m1; }
    __syncthreads();
    float M0 = s0[0], M1 = s1[0];
    #pragma unroll
    for (int i = 1; i < 8; ++i) { M0 = fmaxf(M0, s0[i]); M1 = fmaxf(M1, s1[i]); }

    // ---- block sum of exp(v - max) ----
    float e0 = (t < T_) ? __expf(vb - M0) : 0.0f;
    float e1 = (t < T_ && hasE) ? __expf(ve - M1) : 0.0f;
    #pragma unroll
    for (int o = 16; o > 0; o >>= 1) {
        e0 += __shfl_xor_sync(0xffffffffu, e0, o);
        e1 += __shfl_xor_sync(0xffffffffu, e1, o);
    }
    __syncthreads();               // s0/s1 reuse
    if (lane == 0) { s0[wid] = e0; s1[wid] = e1; }
    __syncthreads();
    float S0 = 0.0f, S1 = 0.0f;
    #pragma unroll
    for (int i = 0; i < 8; ++i) { S0 += s0[i]; S1 += s1[i]; }

    const float lse0 = M0 + __logf(S0);
    const float lse1 = M1 + __logf(S1);   // unused (garbage) when !hasE

    if (t < T_) {
        g_blank[(b * T_ + t) * U_ + u] = (vb - lse0) * LOG2E;
        if (hasE) g_emit[(b * T_ + t) * UM1 + u] = (ve - lse1) * LOG2E;
    }
}

// ---------------------------------------------------------------------------
// Kernel B: anti-diagonal wavefront DP, one block per batch, warp 0 does DP.
// Lane i owns u0=2i and u1=2i+1:
//   left neighbor of u1 is the SAME lane's old p0  -> no shuffle
//   left neighbor of u0 is lane i-1's old p1       -> one shfl_up
// All values log2-domain; logaddexp2 via approx MUFU.
// ---------------------------------------------------------------------------
__global__ __launch_bounds__(256) void k_dp(const int* __restrict__ ilen,
                                            const int* __restrict__ tlen) {
    const int b = blockIdx.x;
    extern __shared__ float smem[];
    float* sb = smem;              // [T_][U_]
    float* se = smem + T_ * U_;    // [T_][UM1]

    {   // vectorized staging (both per-batch slabs are 16B-aligned multiples)
        const float4* gb = (const float4*)(g_blank + b * T_ * U_);
        const float4* ge = (const float4*)(g_emit  + b * T_ * UM1);
        float4* s4b = (float4*)sb;
        float4* s4e = (float4*)se;
        for (int i = threadIdx.x; i < (T_ * U_)  / 4; i += 256) s4b[i] = gb[i];
        for (int i = threadIdx.x; i < (T_ * UM1) / 4; i += 256) s4e[i] = ge[i];
    }
    __syncthreads();
    if (threadIdx.x >= 32) return;      // warp 0 only from here

    const int lane = threadIdx.x;
    const int ti = ilen[b] - 1;         // in [99, 199]
    const int ui = tlen[b] - 1;         // in [24, 49]
    const int u0 = 2 * lane;
    const int u1 = 2 * lane + 1;
    const bool act = (u0 < U_);         // lanes 0..24 active

    float p0 = (lane == 0) ? 0.0f : NEGINF;   // alpha[d-u0][u0] on prev diagonal
    float p1 = NEGINF;                        // alpha[d-u1][u1]

    const int dmax = ti + ui;                 // answer cell sits on the LAST diagonal

    #pragma unroll 4
    for (int d = 1; d <= dmax; ++d) {
        const float lp = __shfl_up_sync(0xffffffffu, p1, 1);  // alpha[t0][u0-1] (old)

        float n0 = NEGINF, n1 = NEGINF;
        const int t0 = d - u0;
        const int t1 = d - u1;

        if (act && t0 >= 0 && t0 < T_) {
            float x = (t0 >= 1) ? p0 + sb[(t0 - 1) * U_ + u0] : NEGINF;
            float y = (u0 >= 1) ? lp + se[t0 * UM1 + (u0 - 1)] : NEGINF;
            n0 = lae2(x, y);
        }
        if (act && t1 >= 0 && t1 < T_) {
            float x = (t1 >= 1) ? p1 + sb[(t1 - 1) * U_ + u1] : NEGINF;
            float y = p0 + se[t1 * UM1 + u0];   // old p0 == alpha[t1][u1-1]
            n1 = lae2(x, y);
        }

        p0 = n0;
        p1 = n1;
    }

    // final diagonal d = dmax holds alpha[ti][ui] in the lane owning ui
    if (act) {
        if (u0 == ui) g_res[b] = -(p0 + sb[ti * U_ + u0]) * LN2;
        if (u1 == ui) g_res[b] = -(p1 + sb[ti * U_ + u1]) * LN2;
    }
}

// ---------------------------------------------------------------------------
// Kernel C: deterministic mean over the 8 batches.
// ---------------------------------------------------------------------------
__global__ void k_final(float* __restrict__ out) {
    if (threadIdx.x == 0) {
        float s = 0.0f;
        #pragma unroll
        for (int i = 0; i < B_; ++i) s += g_res[i];
        out[0] = s * (1.0f / B_);
    }
}

// ---------------------------------------------------------------------------
extern "C" void kernel_launch(void* const* d_in, const int* in_sizes, int n_in,
                              void* d_out, int out_size) {
    const float* h       = (const float*)d_in[0];
    const int*   targets = (const int*)  d_in[1];
    const int*   il      = (const int*)  d_in[2];
    const int*   tl      = (const int*)  d_in[3];
    float*       out     = (float*)d_out;

    const int smem_bytes = (T_ * U_ + T_ * UM1) * (int)sizeof(float);  // 79200
    cudaFuncSetAttribute(k_dp, cudaFuncAttributeMaxDynamicSharedMemorySize, smem_bytes);

    k_lse  <<<B_ * U_, 256>>>(h, targets);
    k_dp   <<<B_, 256, smem_bytes>>>(il, tl);
    k_final<<<1, 32>>>(out);
}

// round 5
// speedup vs baseline: 2.2708x; 2.2695x over previous
#include <cuda_runtime.h>
#include <cstdint>
#include <cstddef>

#define B_   8
#define T_   200
#define U_   50
#define V_   1024
#define UM1  (U_ - 1)
#define PAD  52            // padded row stride for DP slabs (bank-conflict-free-ish)

#define LOG2E 1.4426950408889634f
#define LN2   0.6931471805599453f
#define NEGINF (-1e30f)

// Scratch (allocation-free: __device__ globals). Rows padded to PAD floats.
__device__ float g_blank[B_ * T_ * PAD];   // (b,t,u) log2-domain, stride PAD
__device__ float g_emit [B_ * T_ * PAD];   // (b,t,u) log2-domain, stride PAD
__device__ float g_res  [B_];

__device__ __forceinline__ float ex2a(float x) {
    float r; asm("ex2.approx.f32 %0, %1;" : "=f"(r) : "f"(x)); return r;
}
__device__ __forceinline__ float lg2a(float x) {
    float r; asm("lg2.approx.f32 %0, %1;" : "=f"(r) : "f"(x)); return r;
}
__device__ __forceinline__ float lae2(float x, float y) {   // logaddexp2
    float m = fmaxf(x, y);
    float z = -fabsf(x - y);
    return m + lg2a(1.0f + ex2a(z));
}

// ---------------------------------------------------------------------------
// Kernel A: per-(b,u) gather of blank/emit vocab columns + logsumexp over T.
// Writes PRE-PADDED (stride PAD) log2-domain slabs for the DP kernel.
// ---------------------------------------------------------------------------
__global__ __launch_bounds__(256) void k_lse(const float* __restrict__ h,
                                             const int*   __restrict__ targets) {
    const int bu = blockIdx.x;
    const int b  = bu / U_;
    const int u  = bu % U_;
    const int t  = threadIdx.x;
    const bool hasE = (u < UM1);
    const int  tgt  = hasE ? targets[b * UM1 + u] : 0;

    const float* col = h + ((size_t)b * T_ * U_ + (size_t)u) * V_;

    float vb = NEGINF, ve = NEGINF;
    if (t < T_) {
        const size_t off = (size_t)t * (U_ * V_);
        vb = col[off];                          // blank (v = 0)
        if (hasE) ve = col[off + tgt];          // emit  (v = targets[b,u])
    }

    __shared__ float s0[8], s1[8];
    const int wid  = threadIdx.x >> 5;
    const int lane = threadIdx.x & 31;

    float m0 = vb, m1 = ve;
    #pragma unroll
    for (int o = 16; o > 0; o >>= 1) {
        m0 = fmaxf(m0, __shfl_xor_sync(0xffffffffu, m0, o));
        m1 = fmaxf(m1, __shfl_xor_sync(0xffffffffu, m1, o));
    }
    if (lane == 0) { s0[wid] = m0; s1[wid] = m1; }
    __syncthreads();
    float M0 = s0[0], M1 = s1[0];
    #pragma unroll
    for (int i = 1; i < 8; ++i) { M0 = fmaxf(M0, s0[i]); M1 = fmaxf(M1, s1[i]); }

    float e0 = (t < T_) ? __expf(vb - M0) : 0.0f;
    float e1 = (t < T_ && hasE) ? __expf(ve - M1) : 0.0f;
    #pragma unroll
    for (int o = 16; o > 0; o >>= 1) {
        e0 += __shfl_xor_sync(0xffffffffu, e0, o);
        e1 += __shfl_xor_sync(0xffffffffu, e1, o);
    }
    __syncthreads();
    if (lane == 0) { s0[wid] = e0; s1[wid] = e1; }
    __syncthreads();
    float S0 = 0.0f, S1 = 0.0f;
    #pragma unroll
    for (int i = 0; i < 8; ++i) { S0 += s0[i]; S1 += s1[i]; }

    const float lse0 = M0 + __logf(S0);
    const float lse1 = M1 + __logf(S1);

    if (t < T_) {
        g_blank[(b * T_ + t) * PAD + u] = (vb - lse0) * LOG2E;
        if (hasE) g_emit[(b * T_ + t) * PAD + u] = (ve - lse1) * LOG2E;
    }
}

// ---------------------------------------------------------------------------
// Kernel B: anti-diagonal wavefront DP, one block per batch, warp 0 does DP.
// Lane i owns u0=2i, u1=2i+1. Branchless body (FSEL, clamped addresses).
// Slab rows padded to PAD=52 -> worst 2-way smem conflicts.
// ---------------------------------------------------------------------------
__global__ __launch_bounds__(256) void k_dp(const int* __restrict__ ilen,
                                            const int* __restrict__ tlen) {
    const int b = blockIdx.x;
    extern __shared__ float smem[];
    float* sb = smem;                  // [T_][PAD]
    float* se = smem + T_ * PAD;       // [T_][PAD]

    {
        const float4* gb = (const float4*)(g_blank + b * T_ * PAD);
        const float4* ge = (const float4*)(g_emit  + b * T_ * PAD);
        float4* s4b = (float4*)sb;
        float4* s4e = (float4*)se;
        #pragma unroll 4
        for (int i = threadIdx.x; i < (T_ * PAD) / 4; i += 256) { s4b[i] = gb[i]; s4e[i] = ge[i]; }
    }
    __syncthreads();
    if (threadIdx.x >= 32) return;

    const int lane = threadIdx.x;
    const int ti = ilen[b] - 1;
    const int ui = tlen[b] - 1;
    const int u0 = 2 * lane;
    const int u1 = u0 + 1;
    const int cu0  = min(u0, U_ - 1);          // clamped (ghost lanes)
    const int cu1  = min(u1, U_ - 1);
    const int cu0m = max(min(u0 - 1, U_ - 1), 0);
    const bool lane0 = (lane == 0);

    float p0 = lane0 ? 0.0f : NEGINF;          // alpha[d-u0][u0] on prev diag
    float p1 = NEGINF;                         // alpha[d-u1][u1]

    const int dmax = ti + ui;

    #pragma unroll 4
    for (int d = 1; d <= dmax; ++d) {
        const float lp = __shfl_up_sync(0xffffffffu, p1, 1);  // alpha[t0][u0-1]

        const int t0 = d - u0;                 // cell (t0, u0)
        const int t1 = t0 - 1;                 // cell (t1, u1)
        const int t0c = min(max(t0, 0), T_ - 1);
        const int t0m = min(max(t0 - 1, 0), T_ - 1);
        const int t1c = min(max(t1, 0), T_ - 1);
        const int t1m = min(max(t1 - 1, 0), T_ - 1);

        const float sbA = sb[t0m * PAD + cu0];
        const float seA = se[t0c * PAD + cu0m];
        const float sbB = sb[t1m * PAD + cu1];
        const float seB = se[t1c * PAD + cu0];

        float x0 = (t0 >= 1) ? p0 + sbA : NEGINF;
        float y0 = (!lane0)  ? lp + seA : NEGINF;
        float n0 = lae2(x0, y0);
        n0 = ((unsigned)t0 < (unsigned)T_) ? n0 : NEGINF;

        float x1 = (t1 >= 1) ? p1 + sbB : NEGINF;
        float y1 = p0 + seB;
        float n1 = lae2(x1, y1);
        n1 = ((unsigned)t1 < (unsigned)T_) ? n1 : NEGINF;

        p0 = n0;
        p1 = n1;
    }

    if (u0 == ui) g_res[b] = -(p0 + sb[ti * PAD + u0]) * LN2;
    if (u1 == ui) g_res[b] = -(p1 + sb[ti * PAD + u1]) * LN2;
}

// ---------------------------------------------------------------------------
__global__ void k_final(float* __restrict__ out) {
    if (threadIdx.x == 0) {
        float s = 0.0f;
        #pragma unroll
        for (int i = 0; i < B_; ++i) s += g_res[i];
        out[0] = s * (1.0f / B_);
    }
}

// ---------------------------------------------------------------------------
extern "C" void kernel_launch(void* const* d_in, const int* in_sizes, int n_in,
                              void* d_out, int out_size) {
    const float* h       = (const float*)d_in[0];
    const int*   targets = (const int*)  d_in[1];
    const int*   il      = (const int*)  d_in[2];
    const int*   tl      = (const int*)  d_in[3];
    float*       out     = (float*)d_out;

    const int smem_bytes = 2 * T_ * PAD * (int)sizeof(float);  // 83200
    cudaFuncSetAttribute(k_dp, cudaFuncAttributeMaxDynamicSharedMemorySize, smem_bytes);

    k_lse  <<<B_ * U_, 256>>>(h, targets);
    k_dp   <<<B_, 256, smem_bytes>>>(il, tl);
    k_final<<<1, 32>>>(out);
}

// round 10
// speedup vs baseline: 2.6265x; 1.1566x over previous
#include <cuda_runtime.h>
#include <cstdint>
#include <cstddef>

#define B_   8
#define T_   200
#define U_   50
#define V_   1024
#define UM1  (U_ - 1)

#define ROWS 311            // 62 ghost rows below, 200 data, 49 ghost above
#define PADW 64             // row width (cols 50..63 always zero)
#define SLAB (ROWS * PADW)  // 19904 floats per (batch, slab)

#define LN2   0.6931471805599453f
#define NEGINF (-1e30f)

// __device__ globals are zero-initialized; kernels only write data cells, so
// all margin rows/cols stay exactly 0 forever.
__device__ float g_blank[B_ * SLAB];   // linear probs, row 63+t, col u
__device__ float g_emit [B_ * SLAB];   // linear probs, row 62+t, col u+1
__device__ float g_res  [B_];

__device__ __forceinline__ float lg2a(float x) {
    float r; asm("lg2.approx.f32 %0, %1;" : "=f"(r) : "f"(x)); return r;
}
__device__ __forceinline__ float rcpa(float x) {
    float r; asm("rcp.approx.f32 %0, %1;" : "=f"(r) : "f"(x)); return r;
}

// ---------------------------------------------------------------------------
// Kernel A: warp per (b,u). Gather blank/emit columns (7 t's per lane, all
// loads in flight), softmax over T in registers, store LINEAR probs.
// ---------------------------------------------------------------------------
__global__ __launch_bounds__(256) void k_lse(const float* __restrict__ h,
                                             const int*   __restrict__ targets) {
    const int w    = threadIdx.x >> 5;
    const int lane = threadIdx.x & 31;
    const int bu   = blockIdx.x * 8 + w;          // 0..399
    const int b    = bu / U_;
    const int u    = bu - b * U_;
    const bool hasE = (u < UM1);
    const int  tgt  = hasE ? targets[b * UM1 + u] : 1;

    const float* base = h + ((size_t)(b * T_) * U_ + u) * V_;

    float vb[7], ve[7];
    #pragma unroll
    for (int k = 0; k < 7; ++k) {
        const int t = lane + 32 * k;
        const bool val = (t < T_);
        const float* p = base + (size_t)t * (U_ * V_);
        vb[k] = val ? __ldg(p) : NEGINF;
        ve[k] = (val && hasE) ? __ldg(p + tgt) : NEGINF;
    }

    float M0 = vb[0], M1 = ve[0];
    #pragma unroll
    for (int k = 1; k < 7; ++k) { M0 = fmaxf(M0, vb[k]); M1 = fmaxf(M1, ve[k]); }
    #pragma unroll
    for (int o = 16; o > 0; o >>= 1) {
        M0 = fmaxf(M0, __shfl_xor_sync(0xffffffffu, M0, o));
        M1 = fmaxf(M1, __shfl_xor_sync(0xffffffffu, M1, o));
    }

    float eb[7], ee[7], S0 = 0.0f, S1 = 0.0f;
    #pragma unroll
    for (int k = 0; k < 7; ++k) {
        eb[k] = __expf(vb[k] - M0); S0 += eb[k];   // invalid slots contribute 0
        ee[k] = __expf(ve[k] - M1); S1 += ee[k];
    }
    #pragma unroll
    for (int o = 16; o > 0; o >>= 1) {
        S0 += __shfl_xor_sync(0xffffffffu, S0, o);
        S1 += __shfl_xor_sync(0xffffffffu, S1, o);
    }
    const float r0 = rcpa(S0);
    const float r1 = rcpa(S1);

    float* gb = g_blank + b * SLAB;
    float* ge = g_emit  + b * SLAB;
    #pragma unroll
    for (int k = 0; k < 7; ++k) {
        const int t = lane + 32 * k;
        if (t < T_) {
            gb[(63 + t) * PADW + u] = eb[k] * r0;                  // blank prob
            if (hasE) ge[(62 + t) * PADW + (u + 1)] = ee[k] * r1;  // emit, col+1
        }
    }
}

// ---------------------------------------------------------------------------
// Kernel B: linear-domain scaled forward DP. One block/batch; warp 0 runs
// the anti-diagonal wavefront. Lane i owns u0=2i, u1=2i+1.
//   n0 = p0*B(t0-1,u0) + (lp*fg)*E(t0,u0-1)     lp = left lane's p1 (shfl)
//   n1 = p1*B(t1-1,u1) + p0*E(t1,u1-1)
// Per-lane power-of-2 renorm every 8 steps (integer frame exponent L).
// PER-STEP frame handling (the R7-R9 bug fix): L is shuffled every step;
// inactive lanes adopt the left frame BEFORE fg is computed, so
//   fg = 2^(lL - L) is always the exact conversion between current frames.
// Adoption moves 1 lane/step; the activation front moves 1 lane/2 steps, so
// frames are always current when a lane activates, and |dL| stays far below
// the +-126 clamp with N(0,1)-logit softmax probs.
// Zero margins in the slabs make the body completely guard-free.
// ---------------------------------------------------------------------------
__global__ __launch_bounds__(256) void k_dp(const int* __restrict__ ilen,
                                            const int* __restrict__ tlen) {
    const int b = blockIdx.x;
    extern __shared__ float smem[];
    float* sb = smem;           // [ROWS][PADW] blank slab
    float* se = smem + SLAB;    // [ROWS][PADW] emit slab

    {
        const float4* gb = (const float4*)(g_blank + b * SLAB);
        const float4* ge = (const float4*)(g_emit  + b * SLAB);
        float4* s4 = (float4*)smem;
        #pragma unroll 4
        for (int i = threadIdx.x; i < SLAB / 4; i += 256) {
            s4[i] = gb[i];
            s4[i + SLAB / 4] = ge[i];
        }
    }
    __syncthreads();
    if (threadIdx.x >= 32) return;

    const int lane = threadIdx.x;
    const int ti = ilen[b] - 1;            // [99, 199]
    const int ui = tlen[b] - 1;            // [24, 49]
    const int dmax = ti + ui;

    // coefficient row index for cell (t0 = d - u0, u0) at d = 1:
    int idx = (63 - 2 * lane) * PADW + 2 * lane;

    float p0 = (lane == 0) ? 1.0f : 0.0f;  // alpha[0][0] = 1
    float p1 = 0.0f;
    int   L  = 0;                          // frame exponent: true alpha = p * 2^L

    #define DP_STEP(o)                                                        \
    {                                                                         \
        const float lp  = __shfl_up_sync(0xffffffffu, p1, 1);                 \
        const int   lL  = __shfl_up_sync(0xffffffffu, L, 1);                  \
        const float cbA = sb[o];                                              \
        const float ceA = se[o];                                              \
        const float cbB = sb[(o) - PADW + 1];                                 \
        const float ceB = se[(o) - PADW + 1];                                 \
        if (p0 == 0.0f && p1 == 0.0f) L = lL;   /* adopt left frame */        \
        const int   dL  = min(max(lL - L, -126), 126);                        \
        const float fg  = __uint_as_float((unsigned)(dL + 127) << 23);        \
        const float n0  = fmaf(p0, cbA, (lp * fg) * ceA);                     \
        const float n1  = fmaf(p1, cbB, p0 * ceB);                            \
        p0 = n0; p1 = n1;                                                     \
    }

    const int ngroups = dmax >> 3;
    for (int g = 0; g < ngroups; ++g) {
        #pragma unroll
        for (int k = 0; k < 8; ++k) DP_STEP(idx + k * PADW)
        idx += 8 * PADW;

        // per-lane renorm: bring own max to ~2^0, fold exponent into L
        const float m = fmaxf(p0, p1);
        if (m > 0.0f) {
            const int e = (int)(__float_as_uint(m) >> 23) - 127;
            L += e;
            const float fs = __uint_as_float((unsigned)(127 - e) << 23); // 2^-e
            p0 *= fs; p1 *= fs;
        }
    }

    const int tail = dmax & 7;
    for (int k = 0; k < tail; ++k) DP_STEP(idx + k * PADW)

    #undef DP_STEP

    // answer: alpha[ti][ui] = pf * 2^L ; loss = -(log2(pf*blank) + L)*ln2
    if (lane == (ui >> 1)) {
        const float pf = (ui & 1) ? p1 : p0;
        const float bf = sb[(63 + ti) * PADW + ui];
        g_res[b] = -(lg2a(pf * bf) + (float)L) * LN2;
    }
}

// ---------------------------------------------------------------------------
__global__ void k_final(float* __restrict__ out) {
    if (threadIdx.x == 0) {
        float s = 0.0f;
        #pragma unroll
        for (int i = 0; i < B_; ++i) s += g_res[i];
        out[0] = s * (1.0f / B_);
    }
}

// ---------------------------------------------------------------------------
extern "C" void kernel_launch(void* const* d_in, const int* in_sizes, int n_in,
                              void* d_out, int out_size) {
    const float* h       = (const float*)d_in[0];
    const int*   targets = (const int*)  d_in[1];
    const int*   il      = (const int*)  d_in[2];
    const int*   tl      = (const int*)  d_in[3];
    float*       out     = (float*)d_out;

    const int smem_bytes = 2 * SLAB * (int)sizeof(float);  // 159232
    cudaFuncSetAttribute(k_dp, cudaFuncAttributeMaxDynamicSharedMemorySize, smem_bytes);

    k_lse  <<<B_ * U_ / 8, 256>>>(h, targets);
    k_dp   <<<B_, 256, smem_bytes>>>(il, tl);
    k_final<<<1, 32>>>(out);
}

// round 11
// speedup vs baseline: 3.3093x; 1.2600x over previous
#include <cuda_runtime.h>
#include <cstdint>
#include <cstddef>

#define B_   8
#define T_   200
#define U_   50
#define V_   1024
#define UM1  (U_ - 1)

#define ROWS 311            // 62 ghost rows below, 200 data, 49 ghost above
#define PADW 64             // row width (cols 50..63 always zero)
#define SLAB (ROWS * PADW)  // 19904 floats per (batch, slab)

#define LN2   0.6931471805599453f
#define NEGINF (-1e30f)

// __device__ globals are zero-initialized; kernels only write data cells, so
// all margin rows/cols (and all skipped u > ui columns) stay exactly 0.
__device__ float g_blank[B_ * SLAB];   // linear probs, row 63+t, col u
__device__ float g_emit [B_ * SLAB];   // linear probs, row 62+t, col u+1
__device__ float g_res  [B_];

__device__ __forceinline__ float lg2a(float x) {
    float r; asm("lg2.approx.f32 %0, %1;" : "=f"(r) : "f"(x)); return r;
}
__device__ __forceinline__ float rcpa(float x) {
    float r; asm("rcp.approx.f32 %0, %1;" : "=f"(r) : "f"(x)); return r;
}

// ---------------------------------------------------------------------------
// Kernel A: warp per (b,u). Softmax over full T (required by the reference),
// but warps whose column can never reach the answer cell (u > tlen[b]-1)
// exit before issuing any h loads. 100 blocks x 128 threads for SM spread.
// ---------------------------------------------------------------------------
__global__ __launch_bounds__(128) void k_lse(const float* __restrict__ h,
                                             const int*   __restrict__ targets,
                                             const int*   __restrict__ tlen) {
    const int w    = threadIdx.x >> 5;
    const int lane = threadIdx.x & 31;
    const int bu   = blockIdx.x * 4 + w;          // 0..399
    const int b    = bu / U_;
    const int u    = bu - b * U_;

    const int ui = tlen[b] - 1;                   // in [24, 49]
    if (u > ui) return;                           // column unreachable -> skip
    const bool hasE = (u < ui);                   // emit needed only into cols <= ui
    const int  tgt  = hasE ? targets[b * UM1 + u] : 1;

    const float* base = h + ((size_t)(b * T_) * U_ + u) * V_;

    float vb[7], ve[7];
    #pragma unroll
    for (int k = 0; k < 7; ++k) {
        const int t = lane + 32 * k;
        const bool val = (t < T_);
        const float* p = base + (size_t)t * (U_ * V_);
        vb[k] = val ? __ldg(p) : NEGINF;
        ve[k] = (val && hasE) ? __ldg(p + tgt) : NEGINF;
    }

    float M0 = vb[0], M1 = ve[0];
    #pragma unroll
    for (int k = 1; k < 7; ++k) { M0 = fmaxf(M0, vb[k]); M1 = fmaxf(M1, ve[k]); }
    #pragma unroll
    for (int o = 16; o > 0; o >>= 1) {
        M0 = fmaxf(M0, __shfl_xor_sync(0xffffffffu, M0, o));
        M1 = fmaxf(M1, __shfl_xor_sync(0xffffffffu, M1, o));
    }

    float eb[7], ee[7], S0 = 0.0f, S1 = 0.0f;
    #pragma unroll
    for (int k = 0; k < 7; ++k) {
        eb[k] = __expf(vb[k] - M0); S0 += eb[k];   // invalid slots contribute 0
        ee[k] = __expf(ve[k] - M1); S1 += ee[k];
    }
    #pragma unroll
    for (int o = 16; o > 0; o >>= 1) {
        S0 += __shfl_xor_sync(0xffffffffu, S0, o);
        S1 += __shfl_xor_sync(0xffffffffu, S1, o);
    }
    const float r0 = rcpa(S0);
    const float r1 = rcpa(S1);

    float* gb = g_blank + b * SLAB;
    float* ge = g_emit  + b * SLAB;
    #pragma unroll
    for (int k = 0; k < 7; ++k) {
        const int t = lane + 32 * k;
        if (t < T_) {
            gb[(63 + t) * PADW + u] = eb[k] * r0;                  // blank prob
            if (hasE) ge[(62 + t) * PADW + (u + 1)] = ee[k] * r1;  // emit, col+1
        }
    }
}

// ---------------------------------------------------------------------------
// Kernel B: linear-domain scaled forward DP. One block/batch; warp 0 runs
// the anti-diagonal wavefront. Lane i owns u0=2i, u1=2i+1.
//   n0 = p0*B(t0-1,u0) + lp*E(t0,u0-1)      lp = left lane's p1 (shfl)
//   n1 = p1*B(t1-1,u1) + p0*E(t1,u1-1)
// WARP-UNIFORM frames: every 8 steps, all lanes rescale by the same 2^-e
// (e = exponent of a broadcast reference active lane's p0), accumulated in a
// warp-uniform integer L. Frames never diverge across lanes, so NO per-step
// frame conversion exists in the inner loop (the R10 75-cyc chain is gone).
// Zero margins + zero u>ui columns keep the body guard-free.
// ---------------------------------------------------------------------------
__global__ __launch_bounds__(256) void k_dp(const int* __restrict__ ilen,
                                            const int* __restrict__ tlen) {
    const int b = blockIdx.x;
    extern __shared__ float smem[];
    float* sb = smem;           // [ROWS][PADW] blank slab
    float* se = smem + SLAB;    // [ROWS][PADW] emit slab

    {   // zero ghost rows, copy only the 201 data rows (62..262) of each slab
        float4* s4 = (float4*)smem;
        const float4 z4 = make_float4(0.f, 0.f, 0.f, 0.f);
        const int Q = SLAB / 4;                       // float4 per slab
        for (int i = threadIdx.x; i < 62 * 16; i += 256) {        // rows 0..61
            s4[i] = z4; s4[i + Q] = z4;
        }
        for (int i = threadIdx.x; i < 48 * 16; i += 256) {        // rows 263..310
            s4[263 * 16 + i] = z4; s4[263 * 16 + Q + i] = z4;
        }
        const float4* gb = (const float4*)(g_blank + b * SLAB);
        const float4* ge = (const float4*)(g_emit  + b * SLAB);
        #pragma unroll 4
        for (int i = threadIdx.x; i < 201 * 16; i += 256) {       // rows 62..262
            s4[62 * 16 + i]     = gb[62 * 16 + i];
            s4[62 * 16 + Q + i] = ge[62 * 16 + i];
        }
    }
    __syncthreads();
    if (threadIdx.x >= 32) return;

    const int lane = threadIdx.x;
    const int ti = ilen[b] - 1;            // [99, 199]
    const int ui = tlen[b] - 1;            // [24, 49]
    const int dmax = ti + ui;

    // coefficient row index for cell (t0 = d - u0, u0) at d = 1:
    int idx = (63 - 2 * lane) * PADW + 2 * lane;

    float p0 = (lane == 0) ? 1.0f : 0.0f;  // alpha[0][0] = 1
    float p1 = 0.0f;
    int   L  = 0;                          // warp-uniform frame: alpha = p * 2^L

    #define DP_STEP(o)                                                        \
    {                                                                         \
        const float lp  = __shfl_up_sync(0xffffffffu, p1, 1);                 \
        const float cbA = sb[o];                                              \
        const float ceA = se[o];                                              \
        const float cbB = sb[(o) - PADW + 1];                                 \
        const float ceB = se[(o) - PADW + 1];                                 \
        const float n0  = fmaf(p0, cbA, lp * ceA);                            \
        const float n1  = fmaf(p1, cbB, p0 * ceB);                            \
        p0 = n0; p1 = n1;                                                     \
    }

    const int ngroups = dmax >> 3;
    for (int g = 0; g < ngroups; ++g) {
        #pragma unroll
        for (int k = 0; k < 8; ++k) DP_STEP(idx + k * PADW)
        idx += 8 * PADW;

        // warp-uniform renorm: e from a reference lane that is active and
        // inside the u <= ui region on the last processed diagonal dcur.
        const int dcur = 8 * (g + 1);
        int lo = dcur - (T_ - 1);
        lo = (lo > 0) ? ((lo + 1) >> 1) : 0;
        const int hi  = min(ui >> 1, dcur >> 1);
        const int ref = (lo + hi) >> 1;

        float pr = __shfl_sync(0xffffffffu, p0, ref);
        pr = (pr > 0.0f) ? pr : 1.0f;                 // degenerate: no renorm
        const int e = (int)(__float_as_uint(pr) >> 23) - 127;
        L += e;
        const float fs = __uint_as_float((unsigned)(127 - e) << 23);  // 2^-e
        p0 *= fs; p1 *= fs;
    }

    const int tail = dmax & 7;
    for (int k = 0; k < tail; ++k) DP_STEP(idx + k * PADW)

    #undef DP_STEP

    // answer: alpha[ti][ui] = pf * 2^L ; loss = -(log2(pf*blank) + L)*ln2
    if (lane == (ui >> 1)) {
        const float pf = (ui & 1) ? p1 : p0;
        const float bf = sb[(63 + ti) * PADW + ui];
        g_res[b] = -(lg2a(pf * bf) + (float)L) * LN2;
    }
}

// ---------------------------------------------------------------------------
__global__ void k_final(float* __restrict__ out) {
    if (threadIdx.x == 0) {
        float s = 0.0f;
        #pragma unroll
        for (int i = 0; i < B_; ++i) s += g_res[i];
        out[0] = s * (1.0f / B_);
    }
}

// ---------------------------------------------------------------------------
extern "C" void kernel_launch(void* const* d_in, const int* in_sizes, int n_in,
                              void* d_out, int out_size) {
    const float* h       = (const float*)d_in[0];
    const int*   targets = (const int*)  d_in[1];
    const int*   il      = (const int*)  d_in[2];
    const int*   tl      = (const int*)  d_in[3];
    float*       out     = (float*)d_out;

    const int smem_bytes = 2 * SLAB * (int)sizeof(float);  // 159232
    cudaFuncSetAttribute(k_dp, cudaFuncAttributeMaxDynamicSharedMemorySize, smem_bytes);

    k_lse  <<<B_ * U_ / 4, 128>>>(h, targets, tl);
    k_dp   <<<B_, 256, smem_bytes>>>(il, tl);
    k_final<<<1, 32>>>(out);
}